// round 2
// baseline (speedup 1.0000x reference)
#include <cuda_runtime.h>
#include <math.h>

#define Bsz 512
#define Nn  32
#define Ls  50
#define Hh  256
#define Vv  100000
#define BN  (Bsz*Nn)   // 16384
#define BL  (Bsz*Ls)   // 25600

// ---------------- scratch (static device globals; no allocation) ----------------
__device__ float g_h[BN*Hh];
__device__ float g_hin[BN*Hh];
__device__ float g_hout[BN*Hh];
__device__ float g_a[BN*2*Hh];
__device__ float g_gi[BN*3*Hh];
__device__ float g_gh[BN*3*Hh];
__device__ float g_hseq[(size_t)BL*Hh];
__device__ float g_q2[(size_t)BL*Hh];
__device__ float g_q1[Bsz*Hh];
__device__ float g_htail[Bsz*Hh];
__device__ float g_alpha[BL];
__device__ float g_seqemb[Bsz*Hh];

// ---------------- kernels ----------------

// h[i,:] = emb[items[i],:]
__global__ void embed_gather_kernel(const int* __restrict__ items,
                                    const float* __restrict__ emb) {
    int i = blockIdx.x;
    int item = items[i];
    int t = threadIdx.x; // 64 threads * float4 = 256 floats
    *(float4*)&g_h[(size_t)i*Hh + t*4] =
        *(const float4*)&emb[(size_t)item*Hh + t*4];
}

// C[M,N2] = A[M,K] @ W[K,N2] + bias   (all dims multiples of tile; no guards)
__global__ __launch_bounds__(256) void sgemm_bias_kernel(
    const float* __restrict__ A, const float* __restrict__ W,
    const float* __restrict__ bias, float* __restrict__ C,
    int M, int K, int N) {
    __shared__ float As[8][128];
    __shared__ float Bs[8][128];
    int tid = threadIdx.x;
    int bm = blockIdx.y * 128;
    int bn = blockIdx.x * 128;
    int a_row = tid >> 1;          // 0..127
    int a_col = (tid & 1) * 4;     // 0 or 4
    int w_row = tid >> 5;          // 0..7
    int w_col = (tid & 31) * 4;    // 0..124
    int ty = tid >> 4, tx = tid & 15;

    float acc[8][8];
    #pragma unroll
    for (int i = 0; i < 8; i++)
        #pragma unroll
        for (int j = 0; j < 8; j++) acc[i][j] = 0.f;

    for (int k0 = 0; k0 < K; k0 += 8) {
        float4 av = *(const float4*)(A + (size_t)(bm + a_row) * K + k0 + a_col);
        As[a_col+0][a_row] = av.x;
        As[a_col+1][a_row] = av.y;
        As[a_col+2][a_row] = av.z;
        As[a_col+3][a_row] = av.w;
        float4 wv = *(const float4*)(W + (size_t)(k0 + w_row) * N + bn + w_col);
        *(float4*)&Bs[w_row][w_col] = wv;
        __syncthreads();
        #pragma unroll
        for (int k = 0; k < 8; k++) {
            float ra[8], rb[8];
            *(float4*)(ra)   = *(const float4*)&As[k][ty*8];
            *(float4*)(ra+4) = *(const float4*)&As[k][ty*8+4];
            *(float4*)(rb)   = *(const float4*)&Bs[k][tx*8];
            *(float4*)(rb+4) = *(const float4*)&Bs[k][tx*8+4];
            #pragma unroll
            for (int i = 0; i < 8; i++)
                #pragma unroll
                for (int j = 0; j < 8; j++) acc[i][j] += ra[i] * rb[j];
        }
        __syncthreads();
    }
    #pragma unroll
    for (int i = 0; i < 8; i++) {
        int m = bm + ty*8 + i;
        float4 c0, c1;
        c0.x = acc[i][0] + bias[bn+tx*8+0];
        c0.y = acc[i][1] + bias[bn+tx*8+1];
        c0.z = acc[i][2] + bias[bn+tx*8+2];
        c0.w = acc[i][3] + bias[bn+tx*8+3];
        c1.x = acc[i][4] + bias[bn+tx*8+4];
        c1.y = acc[i][5] + bias[bn+tx*8+5];
        c1.z = acc[i][6] + bias[bn+tx*8+6];
        c1.w = acc[i][7] + bias[bn+tx*8+7];
        *(float4*)(C + (size_t)m*N + bn + tx*8)     = c0;
        *(float4*)(C + (size_t)m*N + bn + tx*8 + 4) = c1;
    }
}

// C[M,N2] = A[M,K] @ Bm[N2,K]^T  (N edge guarded; used for scores)
__global__ __launch_bounds__(256) void sgemm_nt_kernel(
    const float* __restrict__ A, const float* __restrict__ Bm,
    float* __restrict__ C, int M, int N, int K) {
    __shared__ float As[8][128];
    __shared__ float Bs[8][128];
    int tid = threadIdx.x;
    int bm = blockIdx.y * 128;
    int bn = blockIdx.x * 128;
    int lr = tid >> 1;
    int lc = (tid & 1) * 4;
    int ty = tid >> 4, tx = tid & 15;

    float acc[8][8];
    #pragma unroll
    for (int i = 0; i < 8; i++)
        #pragma unroll
        for (int j = 0; j < 8; j++) acc[i][j] = 0.f;

    for (int k0 = 0; k0 < K; k0 += 8) {
        float4 av = *(const float4*)(A + (size_t)(bm + lr) * K + k0 + lc);
        As[lc+0][lr] = av.x;
        As[lc+1][lr] = av.y;
        As[lc+2][lr] = av.z;
        As[lc+3][lr] = av.w;
        int n = bn + lr;
        float4 bv = make_float4(0.f, 0.f, 0.f, 0.f);
        if (n < N) bv = *(const float4*)(Bm + (size_t)n * K + k0 + lc);
        Bs[lc+0][lr] = bv.x;
        Bs[lc+1][lr] = bv.y;
        Bs[lc+2][lr] = bv.z;
        Bs[lc+3][lr] = bv.w;
        __syncthreads();
        #pragma unroll
        for (int k = 0; k < 8; k++) {
            float ra[8], rb[8];
            *(float4*)(ra)   = *(const float4*)&As[k][ty*8];
            *(float4*)(ra+4) = *(const float4*)&As[k][ty*8+4];
            *(float4*)(rb)   = *(const float4*)&Bs[k][tx*8];
            *(float4*)(rb+4) = *(const float4*)&Bs[k][tx*8+4];
            #pragma unroll
            for (int i = 0; i < 8; i++)
                #pragma unroll
                for (int j = 0; j < 8; j++) acc[i][j] += ra[i] * rb[j];
        }
        __syncthreads();
    }
    #pragma unroll
    for (int i = 0; i < 8; i++) {
        int m = bm + ty*8 + i;
        #pragma unroll
        for (int j = 0; j < 8; j++) {
            int n = bn + tx*8 + j;
            if (n < N) C[(size_t)m * N + n] = acc[i][j];
        }
    }
}

// a[b,:, :H] = A_in[b] @ hin[b] ; a[b,:, H:] = A_out[b] @ hout[b]
__global__ void ggnn_msg_kernel(const float* __restrict__ A,
                                const float* __restrict__ hin,
                                const float* __restrict__ hout,
                                float* __restrict__ aout) {
    int b = blockIdx.x;
    __shared__ float sA[32*64];     // 8 KB
    __shared__ float sH[32*256];    // 32 KB
    int t = threadIdx.x;            // 256
    const float* Ab = A + (size_t)b * (Nn * 2 * Nn);
    for (int i = t*4; i < 32*64; i += 1024)
        *(float4*)&sA[i] = *(const float4*)&Ab[i];
    const float* Hin = hin + (size_t)b * Nn * Hh;
    for (int i = t*4; i < 32*256; i += 1024)
        *(float4*)&sH[i] = *(const float4*)&Hin[i];
    __syncthreads();
    float* Ao = aout + (size_t)b * Nn * 2 * Hh;
    for (int n = 0; n < 32; n++) {
        float s = 0.f;
        #pragma unroll
        for (int j = 0; j < 32; j++) s += sA[n*64 + j] * sH[j*256 + t];
        Ao[n*512 + t] = s;
    }
    __syncthreads();
    const float* Hout = hout + (size_t)b * Nn * Hh;
    for (int i = t*4; i < 32*256; i += 1024)
        *(float4*)&sH[i] = *(const float4*)&Hout[i];
    __syncthreads();
    for (int n = 0; n < 32; n++) {
        float s = 0.f;
        #pragma unroll
        for (int j = 0; j < 32; j++) s += sA[n*64 + 32 + j] * sH[j*256 + t];
        Ao[n*512 + 256 + t] = s;
    }
}

// GRU cell elementwise update (in-place on g_h)
__global__ void gru_kernel(const float* __restrict__ gi,
                           const float* __restrict__ gh) {
    int idx = blockIdx.x * blockDim.x + threadIdx.x; // BN*Hh
    int row = idx >> 8;
    int c   = idx & 255;
    size_t o = (size_t)row * (3*Hh) + c;
    float ir = gi[o],       hr = gh[o];
    float iz = gi[o+Hh],    hz = gh[o+Hh];
    float in_ = gi[o+2*Hh], hn = gh[o+2*Hh];
    float r = 1.f / (1.f + expf(-(ir + hr)));
    float z = 1.f / (1.f + expf(-(iz + hz)));
    float ng = tanhf(in_ + r * hn);
    float ho = g_h[idx];
    g_h[idx] = ng + z * (ho - ng);
}

// h_seqs[b,l,:] = h[b, alias[b,l], :]
__global__ void seq_gather_kernel(const int* __restrict__ alias) {
    int bl = blockIdx.x;
    int b = bl / Ls;
    int j = alias[bl];
    int t = threadIdx.x; // 64
    *(float4*)&g_hseq[(size_t)bl*Hh + t*4] =
        *(const float4*)&g_h[((size_t)b*Nn + j)*Hh + t*4];
}

// tail[b] = sum(mask[b])-1; h_tail[b,:] = h[b, alias[b,tail], :]
__global__ void tail_gather_kernel(const int* __restrict__ mask,
                                   const int* __restrict__ alias) {
    int b = blockIdx.x;
    int t = threadIdx.x; // 64
    __shared__ int tail;
    if (t == 0) {
        int s = 0;
        for (int l = 0; l < Ls; l++) s += mask[b*Ls + l];
        tail = s - 1;
    }
    __syncthreads();
    int j = alias[b*Ls + tail];
    *(float4*)&g_htail[(size_t)b*Hh + t*4] =
        *(const float4*)&g_h[((size_t)b*Nn + j)*Hh + t*4];
}

// alpha[b,l] = sigmoid(q1[b]+q2[b,l]) . fc3
__global__ void attn_alpha_kernel(const float* __restrict__ fc3) {
    int bl = blockIdx.x;
    int b = bl / Ls;
    int t = threadIdx.x; // 256
    float x = g_q1[(size_t)b*Hh + t] + g_q2[(size_t)bl*Hh + t];
    float s = 1.f / (1.f + expf(-x));
    float v = s * fc3[t];
    __shared__ float red[8];
    #pragma unroll
    for (int o = 16; o > 0; o >>= 1) v += __shfl_down_sync(0xffffffffu, v, o);
    if ((t & 31) == 0) red[t >> 5] = v;
    __syncthreads();
    if (t == 0) {
        float s2 = 0.f;
        #pragma unroll
        for (int i = 0; i < 8; i++) s2 += red[i];
        g_alpha[bl] = s2;
    }
}

// seq_emb[b,:] = sum_l alpha[b,l]*mask[b,l]*h_seqs[b,l,:]
__global__ void attn_pool_kernel(const int* __restrict__ mask) {
    int b = blockIdx.x;
    int h = threadIdx.x; // 256
    __shared__ float am[Ls];
    if (h < Ls) am[h] = g_alpha[b*Ls + h] * (float)mask[b*Ls + h];
    __syncthreads();
    float s = 0.f;
    #pragma unroll
    for (int l = 0; l < Ls; l++)
        s += am[l] * g_hseq[((size_t)b*Ls + l)*Hh + h];
    g_seqemb[(size_t)b*Hh + h] = s;
}

// ---------------- launch ----------------
extern "C" void kernel_launch(void* const* d_in, const int* in_sizes, int n_in,
                              void* d_out, int out_size) {
    const float* A      = (const float*)d_in[0];
    const int*   items  = (const int*)d_in[1];
    const int*   alias  = (const int*)d_in[2];
    const int*   mask   = (const int*)d_in[3];
    const float* emb    = (const float*)d_in[4];
    const float* W_in   = (const float*)d_in[5];
    const float* b_in   = (const float*)d_in[6];
    const float* W_out  = (const float*)d_in[7];
    const float* b_out  = (const float*)d_in[8];
    const float* W_ih   = (const float*)d_in[9];
    const float* b_ih   = (const float*)d_in[10];
    const float* W_hh   = (const float*)d_in[11];
    const float* b_hh   = (const float*)d_in[12];
    const float* fc1w   = (const float*)d_in[13];
    const float* fc1b   = (const float*)d_in[14];
    const float* fc2w   = (const float*)d_in[15];
    const float* fc2b   = (const float*)d_in[16];
    const float* fc3w   = (const float*)d_in[17];
    float* out = (float*)d_out;

    float *p_h, *p_hin, *p_hout, *p_a, *p_gi, *p_gh, *p_hseq, *p_q2, *p_q1,
          *p_htail, *p_seqemb;
    cudaGetSymbolAddress((void**)&p_h,      g_h);
    cudaGetSymbolAddress((void**)&p_hin,    g_hin);
    cudaGetSymbolAddress((void**)&p_hout,   g_hout);
    cudaGetSymbolAddress((void**)&p_a,      g_a);
    cudaGetSymbolAddress((void**)&p_gi,     g_gi);
    cudaGetSymbolAddress((void**)&p_gh,     g_gh);
    cudaGetSymbolAddress((void**)&p_hseq,   g_hseq);
    cudaGetSymbolAddress((void**)&p_q2,     g_q2);
    cudaGetSymbolAddress((void**)&p_q1,     g_q1);
    cudaGetSymbolAddress((void**)&p_htail,  g_htail);
    cudaGetSymbolAddress((void**)&p_seqemb, g_seqemb);

    // 1. h0 = emb[items]
    embed_gather_kernel<<<BN, 64>>>(items, emb);
    // 2-3. hin = h@W_in+b_in ; hout = h@W_out+b_out
    sgemm_bias_kernel<<<dim3(Hh/128, BN/128), 256>>>(p_h, W_in,  b_in,  p_hin,  BN, Hh, Hh);
    sgemm_bias_kernel<<<dim3(Hh/128, BN/128), 256>>>(p_h, W_out, b_out, p_hout, BN, Hh, Hh);
    // 4. message passing (batched small matmul) -> concat a
    ggnn_msg_kernel<<<Bsz, 256>>>(A, p_hin, p_hout, p_a);
    // 5-6. GRU gates
    sgemm_bias_kernel<<<dim3(3*Hh/128, BN/128), 256>>>(p_a, W_ih, b_ih, p_gi, BN, 2*Hh, 3*Hh);
    sgemm_bias_kernel<<<dim3(3*Hh/128, BN/128), 256>>>(p_h, W_hh, b_hh, p_gh, BN, Hh, 3*Hh);
    // 7. GRU cell update (in place on g_h)
    gru_kernel<<<BN*Hh/256, 256>>>(p_gi, p_gh);
    // 8. gather session sequences
    seq_gather_kernel<<<BL, 64>>>(alias);
    // 9. tail hidden state
    tail_gather_kernel<<<Bsz, 64>>>(mask, alias);
    // 10-11. attention projections
    sgemm_bias_kernel<<<dim3(Hh/128, BL/128), 256>>>(p_hseq, fc2w, fc2b, p_q2, BL, Hh, Hh);
    sgemm_bias_kernel<<<dim3(Hh/128, Bsz/128), 256>>>(p_htail, fc1w, fc1b, p_q1, Bsz, Hh, Hh);
    // 12. alpha
    attn_alpha_kernel<<<BL, 256>>>(fc3w);
    // 13. pooled session embedding
    attn_pool_kernel<<<Bsz, 256>>>(mask);
    // 14. scores = seq_emb @ emb[1:]^T
    sgemm_nt_kernel<<<dim3((Vv + 127)/128, Bsz/128), 256>>>(p_seqemb, emb + Hh, out, Bsz, Vv, Hh);
}

// round 3
// speedup vs baseline: 2.2037x; 2.2037x over previous
#include <cuda_runtime.h>
#include <cuda_bf16.h>
#include <math.h>
#include <stdint.h>

#define Bsz 512
#define Nn  32
#define Ls  50
#define Hh  256
#define Vv  100000
#define BN  (Bsz*Nn)   // 16384
#define BL  (Bsz*Ls)   // 25600

// ---------------- scratch (static device globals; no allocation) ----------------
__device__ float g_h[BN*Hh];                       // node hidden states
__device__ float g_f[(size_t)BN*1280];             // fused [hin | hout | gh]
__device__ float g_a[(size_t)BN*2*Hh];             // GRU input (messages)
__device__ float g_gi[(size_t)BN*3*Hh];
__device__ float g_hseq[(size_t)BL*Hh];
__device__ float g_q2[(size_t)BL*Hh];
__device__ float g_q1[Bsz*Hh];
__device__ float g_htail[Bsz*Hh];
__device__ float g_alpha[BL];
__device__ float g_seqemb[Bsz*Hh];

// pre-split / pre-transposed operands (bf16 hi/lo pairs, [N][K] layout)
__device__ __nv_bfloat16 g_WtF_hi[1280*256], g_WtF_lo[1280*256];
__device__ float g_biasF[1280];
__device__ __nv_bfloat16 g_WihT_hi[768*512], g_WihT_lo[768*512];
__device__ __nv_bfloat16 g_fc1T_hi[256*256], g_fc1T_lo[256*256];
__device__ __nv_bfloat16 g_fc2T_hi[256*256], g_fc2T_lo[256*256];
__device__ __nv_bfloat16 g_embT_hi[(size_t)Vv*Hh], g_embT_lo[(size_t)Vv*Hh];

// ---------------- helpers ----------------
__device__ __forceinline__ void ldsm4(uint32_t &r0, uint32_t &r1, uint32_t &r2, uint32_t &r3,
                                      const __nv_bfloat16* p) {
    uint32_t addr = (uint32_t)__cvta_generic_to_shared(p);
    asm volatile("ldmatrix.sync.aligned.m8n8.x4.shared.b16 {%0,%1,%2,%3}, [%4];"
                 : "=r"(r0), "=r"(r1), "=r"(r2), "=r"(r3) : "r"(addr));
}

__device__ __forceinline__ void mma_bf16(float* c, const uint32_t* a, uint32_t b0, uint32_t b1) {
    asm volatile("mma.sync.aligned.m16n8k16.row.col.f32.bf16.bf16.f32 "
                 "{%0,%1,%2,%3}, {%4,%5,%6,%7}, {%8,%9}, {%0,%1,%2,%3};"
                 : "+f"(c[0]), "+f"(c[1]), "+f"(c[2]), "+f"(c[3])
                 : "r"(a[0]), "r"(a[1]), "r"(a[2]), "r"(a[3]), "r"(b0), "r"(b1));
}

__device__ __forceinline__ void split2(float x, __nv_bfloat16 &h, __nv_bfloat16 &l) {
    h = __float2bfloat16(x);
    l = __float2bfloat16(x - __bfloat162float(h));
}

// ---------------- prepack kernels ----------------
__global__ void split_emb_kernel(const float* __restrict__ emb) {
    size_t i = ((size_t)blockIdx.x * 256 + threadIdx.x) * 4;   // over Vv*Hh
    float4 v = *(const float4*)&emb[Hh + i];                   // skip padding row 0
    __nv_bfloat16 h0, l0, h1, l1, h2, l2, h3, l3;
    split2(v.x, h0, l0); split2(v.y, h1, l1); split2(v.z, h2, l2); split2(v.w, h3, l3);
    __nv_bfloat162 hp0; hp0.x = h0; hp0.y = h1;
    __nv_bfloat162 hp1; hp1.x = h2; hp1.y = h3;
    __nv_bfloat162 lp0; lp0.x = l0; lp0.y = l1;
    __nv_bfloat162 lp1; lp1.x = l2; lp1.y = l3;
    *(__nv_bfloat162*)&g_embT_hi[i]   = hp0;
    *(__nv_bfloat162*)&g_embT_hi[i+2] = hp1;
    *(__nv_bfloat162*)&g_embT_lo[i]   = lp0;
    *(__nv_bfloat162*)&g_embT_lo[i+2] = lp1;
}

// generic transpose + split: out[n][k] = W[k][n]
__global__ void pack_t_kernel(const float* __restrict__ W, __nv_bfloat16* __restrict__ hi,
                              __nv_bfloat16* __restrict__ lo, int K, int N) {
    int n = blockIdx.x;
    for (int k = threadIdx.x; k < K; k += blockDim.x) {
        float v = W[(size_t)k * N + n];
        __nv_bfloat16 h, l; split2(v, h, l);
        hi[(size_t)n * K + k] = h;
        lo[(size_t)n * K + k] = l;
    }
}

// fused [W_in | W_out | W_hh]^T -> [1280][256] + packed bias
__global__ void pack_fused_kernel(const float* __restrict__ Win, const float* __restrict__ bin,
                                  const float* __restrict__ Wout, const float* __restrict__ bout,
                                  const float* __restrict__ Whh, const float* __restrict__ bhh) {
    int n = blockIdx.x;   // 0..1279
    int k = threadIdx.x;  // 0..255
    float v;
    if (n < 256)      v = Win[(size_t)k * 256 + n];
    else if (n < 512) v = Wout[(size_t)k * 256 + (n - 256)];
    else              v = Whh[(size_t)k * 768 + (n - 512)];
    __nv_bfloat16 h, l; split2(v, h, l);
    g_WtF_hi[n * 256 + k] = h;
    g_WtF_lo[n * 256 + k] = l;
    if (k == 0)
        g_biasF[n] = (n < 256) ? bin[n] : (n < 512 ? bout[n - 256] : bhh[n - 512]);
}

// ---------------- unified tensor-core GEMM ----------------
// C[M,N] = A[M,K] @ B^T + bias, B pre-split bf16 [N][K], bf16x3 emulation.
// Block 128x128, 8 warps (4x2), warp tile 32x64, k-chunk 32.
#define KST 40   // smem row stride in bf16 (80B, 16B aligned, conflict-free LDSM)

__global__ __launch_bounds__(256) void mma_gemm_nt(
    const float* __restrict__ A, const __nv_bfloat16* __restrict__ Bhi,
    const __nv_bfloat16* __restrict__ Blo, const float* __restrict__ bias,
    float* __restrict__ C, int M, int N, int K) {
    __shared__ __nv_bfloat16 As_hi[128 * KST];
    __shared__ __nv_bfloat16 As_lo[128 * KST];
    __shared__ __nv_bfloat16 Bs_hi[128 * KST];
    __shared__ __nv_bfloat16 Bs_lo[128 * KST];

    int tid = threadIdx.x;
    int lane = tid & 31;
    int wid = tid >> 5;
    int wm = wid >> 1;       // 0..3
    int wn = wid & 1;        // 0..1
    int bm = blockIdx.y * 128;
    int bn = blockIdx.x * 128;

    // ldmatrix per-thread address pattern (shared by A and B frags)
    int lr = (lane & 7) + ((lane >> 3) & 1) * 8;  // row within 16
    int lk = (lane >> 4) * 8;                     // 0 or 8

    float acc[2][8][4];
    #pragma unroll
    for (int i = 0; i < 2; i++)
        #pragma unroll
        for (int j = 0; j < 8; j++)
            #pragma unroll
            for (int q = 0; q < 4; q++) acc[i][j][q] = 0.f;

    int srow = tid >> 3;            // 0..31
    int skk  = (tid & 7) * 4;       // 0..28

    for (int k0 = 0; k0 < K; k0 += 32) {
        // stage A (fp32 -> split bf16)
        #pragma unroll
        for (int it = 0; it < 4; it++) {
            int row = srow + it * 32;
            float4 v = *(const float4*)(A + (size_t)(bm + row) * K + k0 + skk);
            __nv_bfloat16 h0, l0, h1, l1, h2, l2, h3, l3;
            split2(v.x, h0, l0); split2(v.y, h1, l1);
            split2(v.z, h2, l2); split2(v.w, h3, l3);
            __nv_bfloat162 hp0; hp0.x = h0; hp0.y = h1;
            __nv_bfloat162 hp1; hp1.x = h2; hp1.y = h3;
            __nv_bfloat162 lp0; lp0.x = l0; lp0.y = l1;
            __nv_bfloat162 lp1; lp1.x = l2; lp1.y = l3;
            *(__nv_bfloat162*)&As_hi[row * KST + skk]     = hp0;
            *(__nv_bfloat162*)&As_hi[row * KST + skk + 2] = hp1;
            *(__nv_bfloat162*)&As_lo[row * KST + skk]     = lp0;
            *(__nv_bfloat162*)&As_lo[row * KST + skk + 2] = lp1;
        }
        // stage B (already bf16; N-guarded)
        #pragma unroll
        for (int it = 0; it < 4; it++) {
            int n = srow + it * 32;
            uint2 vh = make_uint2(0u, 0u), vl = make_uint2(0u, 0u);
            if (bn + n < N) {
                vh = *(const uint2*)(Bhi + (size_t)(bn + n) * K + k0 + skk);
                vl = *(const uint2*)(Blo + (size_t)(bn + n) * K + k0 + skk);
            }
            *(uint2*)&Bs_hi[n * KST + skk] = vh;
            *(uint2*)&Bs_lo[n * KST + skk] = vl;
        }
        __syncthreads();

        #pragma unroll
        for (int s = 0; s < 2; s++) {
            uint32_t ah[2][4], al[2][4];
            #pragma unroll
            for (int mt = 0; mt < 2; mt++) {
                const __nv_bfloat16* pa = &As_hi[(wm * 32 + mt * 16 + lr) * KST + s * 16 + lk];
                ldsm4(ah[mt][0], ah[mt][1], ah[mt][2], ah[mt][3], pa);
                const __nv_bfloat16* pl = &As_lo[(wm * 32 + mt * 16 + lr) * KST + s * 16 + lk];
                ldsm4(al[mt][0], al[mt][1], al[mt][2], al[mt][3], pl);
            }
            #pragma unroll
            for (int p = 0; p < 4; p++) {
                uint32_t bh[4], bl[4];
                const __nv_bfloat16* pb = &Bs_hi[(wn * 64 + p * 16 + lr) * KST + s * 16 + lk];
                ldsm4(bh[0], bh[1], bh[2], bh[3], pb);
                const __nv_bfloat16* pbl = &Bs_lo[(wn * 64 + p * 16 + lr) * KST + s * 16 + lk];
                ldsm4(bl[0], bl[1], bl[2], bl[3], pbl);
                #pragma unroll
                for (int mt = 0; mt < 2; mt++) {
                    #pragma unroll
                    for (int q = 0; q < 2; q++) {
                        int nt = p * 2 + q;
                        mma_bf16(acc[mt][nt], ah[mt], bh[q], bh[2 + q]);   // hi*hi
                        mma_bf16(acc[mt][nt], ah[mt], bl[q], bl[2 + q]);   // hi*lo
                        mma_bf16(acc[mt][nt], al[mt], bh[q], bh[2 + q]);   // lo*hi
                    }
                }
            }
        }
        __syncthreads();
    }

    // epilogue
    int r0 = lane >> 2;
    int c0 = (lane & 3) * 2;
    #pragma unroll
    for (int mt = 0; mt < 2; mt++) {
        #pragma unroll
        for (int nt = 0; nt < 8; nt++) {
            int col = bn + wn * 64 + nt * 8 + c0;
            if (col >= N) continue;
            float bv0 = bias ? bias[col] : 0.f;
            float bv1 = bias ? bias[col + 1] : 0.f;
            int row = bm + wm * 32 + mt * 16 + r0;
            float2 v0; v0.x = acc[mt][nt][0] + bv0; v0.y = acc[mt][nt][1] + bv1;
            *(float2*)(C + (size_t)row * N + col) = v0;
            float2 v1; v1.x = acc[mt][nt][2] + bv0; v1.y = acc[mt][nt][3] + bv1;
            *(float2*)(C + (size_t)(row + 8) * N + col) = v1;
        }
    }
}

// ---------------- small kernels ----------------
__global__ void embed_gather_kernel(const int* __restrict__ items,
                                    const float* __restrict__ emb) {
    int i = blockIdx.x;
    int item = items[i];
    int t = threadIdx.x;
    *(float4*)&g_h[(size_t)i*Hh + t*4] =
        *(const float4*)&emb[(size_t)item*Hh + t*4];
}

// a[b,:, :H] = A_in[b] @ hin[b] ; a[b,:, H:] = A_out[b] @ hout[b]
// hin/hout live in g_f (row stride 1280, col offsets 0 / 256)
__global__ void ggnn_msg_kernel(const float* __restrict__ A,
                                const float* __restrict__ f,
                                float* __restrict__ aout) {
    int b = blockIdx.x;
    __shared__ float sA[32*64];
    __shared__ float sH[32*256];
    int t = threadIdx.x;            // 256
    const float* Ab = A + (size_t)b * (Nn * 2 * Nn);
    for (int i = t*4; i < 32*64; i += 1024)
        *(float4*)&sA[i] = *(const float4*)&Ab[i];
    const float* Fb = f + (size_t)b * Nn * 1280;
    for (int idx = t; idx < 2048; idx += 256) {   // 32 rows x 64 float4
        int row = idx >> 6, c4 = (idx & 63) * 4;
        *(float4*)&sH[row*256 + c4] = *(const float4*)&Fb[(size_t)row*1280 + c4];
    }
    __syncthreads();
    float* Ao = aout + (size_t)b * Nn * 2 * Hh;
    for (int n = 0; n < 32; n++) {
        float s = 0.f;
        #pragma unroll
        for (int j = 0; j < 32; j++) s += sA[n*64 + j] * sH[j*256 + t];
        Ao[n*512 + t] = s;
    }
    __syncthreads();
    for (int idx = t; idx < 2048; idx += 256) {
        int row = idx >> 6, c4 = (idx & 63) * 4;
        *(float4*)&sH[row*256 + c4] = *(const float4*)&Fb[(size_t)row*1280 + 256 + c4];
    }
    __syncthreads();
    for (int n = 0; n < 32; n++) {
        float s = 0.f;
        #pragma unroll
        for (int j = 0; j < 32; j++) s += sA[n*64 + 32 + j] * sH[j*256 + t];
        Ao[n*512 + 256 + t] = s;
    }
}

// GRU cell (gh lives in g_f at col offset 512, row stride 1280)
__global__ void gru_kernel(const float* __restrict__ gi,
                           const float* __restrict__ f) {
    int idx = blockIdx.x * blockDim.x + threadIdx.x;
    int row = idx >> 8;
    int c   = idx & 255;
    size_t oi = (size_t)row * (3*Hh) + c;
    size_t oh = (size_t)row * 1280 + 512 + c;
    float ir = gi[oi],       hr = f[oh];
    float iz = gi[oi+Hh],    hz = f[oh+Hh];
    float in_ = gi[oi+2*Hh], hn = f[oh+2*Hh];
    float r = 1.f / (1.f + expf(-(ir + hr)));
    float z = 1.f / (1.f + expf(-(iz + hz)));
    float ng = tanhf(in_ + r * hn);
    float ho = g_h[idx];
    g_h[idx] = ng + z * (ho - ng);
}

__global__ void seq_gather_kernel(const int* __restrict__ alias) {
    int bl = blockIdx.x;
    int b = bl / Ls;
    int j = alias[bl];
    int t = threadIdx.x;
    *(float4*)&g_hseq[(size_t)bl*Hh + t*4] =
        *(const float4*)&g_h[((size_t)b*Nn + j)*Hh + t*4];
}

__global__ void tail_gather_kernel(const int* __restrict__ mask,
                                   const int* __restrict__ alias) {
    int b = blockIdx.x;
    int t = threadIdx.x;
    __shared__ int tail;
    if (t == 0) {
        int s = 0;
        for (int l = 0; l < Ls; l++) s += mask[b*Ls + l];
        tail = s - 1;
    }
    __syncthreads();
    int j = alias[b*Ls + tail];
    *(float4*)&g_htail[(size_t)b*Hh + t*4] =
        *(const float4*)&g_h[((size_t)b*Nn + j)*Hh + t*4];
}

__global__ void attn_alpha_kernel(const float* __restrict__ fc3) {
    int bl = blockIdx.x;
    int b = bl / Ls;
    int t = threadIdx.x;
    float x = g_q1[(size_t)b*Hh + t] + g_q2[(size_t)bl*Hh + t];
    float s = 1.f / (1.f + expf(-x));
    float v = s * fc3[t];
    __shared__ float red[8];
    #pragma unroll
    for (int o = 16; o > 0; o >>= 1) v += __shfl_down_sync(0xffffffffu, v, o);
    if ((t & 31) == 0) red[t >> 5] = v;
    __syncthreads();
    if (t == 0) {
        float s2 = 0.f;
        #pragma unroll
        for (int i = 0; i < 8; i++) s2 += red[i];
        g_alpha[bl] = s2;
    }
}

__global__ void attn_pool_kernel(const int* __restrict__ mask) {
    int b = blockIdx.x;
    int h = threadIdx.x;
    __shared__ float am[Ls];
    if (h < Ls) am[h] = g_alpha[b*Ls + h] * (float)mask[b*Ls + h];
    __syncthreads();
    float s = 0.f;
    #pragma unroll
    for (int l = 0; l < Ls; l++)
        s += am[l] * g_hseq[((size_t)b*Ls + l)*Hh + h];
    g_seqemb[(size_t)b*Hh + h] = s;
}

// ---------------- launch ----------------
extern "C" void kernel_launch(void* const* d_in, const int* in_sizes, int n_in,
                              void* d_out, int out_size) {
    const float* A      = (const float*)d_in[0];
    const int*   items  = (const int*)d_in[1];
    const int*   alias  = (const int*)d_in[2];
    const int*   mask   = (const int*)d_in[3];
    const float* emb    = (const float*)d_in[4];
    const float* W_in   = (const float*)d_in[5];
    const float* b_in   = (const float*)d_in[6];
    const float* W_out  = (const float*)d_in[7];
    const float* b_out  = (const float*)d_in[8];
    const float* W_ih   = (const float*)d_in[9];
    const float* b_ih   = (const float*)d_in[10];
    const float* W_hh   = (const float*)d_in[11];
    const float* b_hh   = (const float*)d_in[12];
    const float* fc1w   = (const float*)d_in[13];
    const float* fc1b   = (const float*)d_in[14];
    const float* fc2w   = (const float*)d_in[15];
    const float* fc2b   = (const float*)d_in[16];
    const float* fc3w   = (const float*)d_in[17];
    float* out = (float*)d_out;

    float *p_h, *p_f, *p_a, *p_gi, *p_hseq, *p_q2, *p_q1, *p_htail, *p_seqemb, *p_biasF;
    __nv_bfloat16 *p_WtF_hi, *p_WtF_lo, *p_WihT_hi, *p_WihT_lo,
                  *p_fc1T_hi, *p_fc1T_lo, *p_fc2T_hi, *p_fc2T_lo,
                  *p_embT_hi, *p_embT_lo;
    cudaGetSymbolAddress((void**)&p_h,      g_h);
    cudaGetSymbolAddress((void**)&p_f,      g_f);
    cudaGetSymbolAddress((void**)&p_a,      g_a);
    cudaGetSymbolAddress((void**)&p_gi,     g_gi);
    cudaGetSymbolAddress((void**)&p_hseq,   g_hseq);
    cudaGetSymbolAddress((void**)&p_q2,     g_q2);
    cudaGetSymbolAddress((void**)&p_q1,     g_q1);
    cudaGetSymbolAddress((void**)&p_htail,  g_htail);
    cudaGetSymbolAddress((void**)&p_seqemb, g_seqemb);
    cudaGetSymbolAddress((void**)&p_biasF,  g_biasF);
    cudaGetSymbolAddress((void**)&p_WtF_hi, g_WtF_hi);
    cudaGetSymbolAddress((void**)&p_WtF_lo, g_WtF_lo);
    cudaGetSymbolAddress((void**)&p_WihT_hi, g_WihT_hi);
    cudaGetSymbolAddress((void**)&p_WihT_lo, g_WihT_lo);
    cudaGetSymbolAddress((void**)&p_fc1T_hi, g_fc1T_hi);
    cudaGetSymbolAddress((void**)&p_fc1T_lo, g_fc1T_lo);
    cudaGetSymbolAddress((void**)&p_fc2T_hi, g_fc2T_hi);
    cudaGetSymbolAddress((void**)&p_fc2T_lo, g_fc2T_lo);
    cudaGetSymbolAddress((void**)&p_embT_hi, g_embT_hi);
    cudaGetSymbolAddress((void**)&p_embT_lo, g_embT_lo);

    // --- prepack (independent of activations) ---
    split_emb_kernel<<<(Vv*Hh)/1024, 256>>>(emb);
    pack_fused_kernel<<<1280, 256>>>(W_in, b_in, W_out, b_out, W_hh, b_hh);
    pack_t_kernel<<<768, 256>>>(W_ih, p_WihT_hi, p_WihT_lo, 512, 768);
    pack_t_kernel<<<256, 256>>>(fc1w, p_fc1T_hi, p_fc1T_lo, 256, 256);
    pack_t_kernel<<<256, 256>>>(fc2w, p_fc2T_hi, p_fc2T_lo, 256, 256);

    // --- GGNN layer ---
    embed_gather_kernel<<<BN, 64>>>(items, emb);
    // fused [hin|hout|gh] = h @ [W_in|W_out|W_hh] + bias
    mma_gemm_nt<<<dim3(1280/128, BN/128), 256>>>(p_h, p_WtF_hi, p_WtF_lo, p_biasF, p_f, BN, 1280, 256);
    ggnn_msg_kernel<<<Bsz, 256>>>(A, p_f, p_a);
    mma_gemm_nt<<<dim3(768/128, BN/128), 256>>>(p_a, p_WihT_hi, p_WihT_lo, b_ih, p_gi, BN, 768, 512);
    gru_kernel<<<BN*Hh/256, 256>>>(p_gi, p_f);

    // --- attention pooling ---
    seq_gather_kernel<<<BL, 64>>>(alias);
    tail_gather_kernel<<<Bsz, 64>>>(mask, alias);
    mma_gemm_nt<<<dim3(256/128, BL/128), 256>>>(p_hseq, p_fc2T_hi, p_fc2T_lo, fc2b, p_q2, BL, 256, 256);
    mma_gemm_nt<<<dim3(256/128, Bsz/128), 256>>>(p_htail, p_fc1T_hi, p_fc1T_lo, fc1b, p_q1, Bsz, 256, 256);
    attn_alpha_kernel<<<BL, 256>>>(fc3w);
    attn_pool_kernel<<<Bsz, 256>>>(mask);

    // --- scores = seq_emb @ emb[1:]^T ---
    mma_gemm_nt<<<dim3((Vv + 127)/128, Bsz/128), 256>>>(p_seqemb, p_embT_hi, p_embT_lo, nullptr, out, Bsz, Vv, Hh);
}